// round 1
// baseline (speedup 1.0000x reference)
#include <cuda_runtime.h>
#include <cstddef>

// ---------------------------------------------------------------------------
// NeuralODE dopri5, 16 fixed steps.
//   f(y) = tanh(y @ W1 + b1) @ W2 + b2
//   per step: 6 stages (k1..k6), then y += dt * (B1 k1 + B3 k3 + B4 k4 + B5 k5 + B6 k6)
//   output: y @ Wfc + bfc   -> [B, 1]
// Shapes: B=16384, D=256, H=512.
// ---------------------------------------------------------------------------

#define BROWS 16384
#define DIM   256
#define HID   512
#define NSTEPS 16

// Scratch (static device arrays; no allocation at runtime).
__device__ float g_y  [BROWS * DIM];           // state
__device__ float g_tmp[BROWS * DIM];           // stage input ytmp
__device__ float g_h  [BROWS * HID];           // hidden activations
__device__ float g_k  [6][BROWS * DIM];        // k1..k6

// ---------------------------------------------------------------------------
// Classic fp32 SGEMM: C[M,N] = A[M,K] * B[K,N] (+ bias, optional tanh)
// Tile 128x128x16, 256 threads, 8x8 per thread.
// M % 128 == 0, N % 128 == 0, K % 16 == 0 guaranteed by the shapes here.
// ---------------------------------------------------------------------------
template<bool TANH>
__global__ __launch_bounds__(256, 2)
void sgemm_bias(const float* __restrict__ A, const float* __restrict__ B,
                const float* __restrict__ bias, float* __restrict__ C,
                int M, int N, int K)
{
    __shared__ float As[16][132];   // transposed A tile, padded
    __shared__ float Bs[16][128];

    const int tid = threadIdx.x;
    const int tx  = tid & 15;       // 0..15 -> N direction
    const int ty  = tid >> 4;       // 0..15 -> M direction
    const int m0  = blockIdx.y * 128;
    const int n0  = blockIdx.x * 128;

    float acc[8][8];
#pragma unroll
    for (int i = 0; i < 8; i++)
#pragma unroll
        for (int j = 0; j < 8; j++) acc[i][j] = 0.f;

    for (int k0 = 0; k0 < K; k0 += 16) {
        // Load A tile (128 rows x 16 cols) as 512 float4, 2 per thread; store transposed.
#pragma unroll
        for (int l = 0; l < 2; l++) {
            int f   = tid + l * 256;
            int row = f >> 2;
            int c4  = (f & 3) * 4;
            float4 v = *(const float4*)(A + (size_t)(m0 + row) * K + k0 + c4);
            As[c4 + 0][row] = v.x;
            As[c4 + 1][row] = v.y;
            As[c4 + 2][row] = v.z;
            As[c4 + 3][row] = v.w;
        }
        // Load B tile (16 rows x 128 cols) as 512 float4, 2 per thread.
#pragma unroll
        for (int l = 0; l < 2; l++) {
            int f  = tid + l * 256;
            int kr = f >> 5;
            int c4 = (f & 31) * 4;
            *(float4*)(&Bs[kr][c4]) =
                *(const float4*)(B + (size_t)(k0 + kr) * N + n0 + c4);
        }
        __syncthreads();

#pragma unroll
        for (int kk = 0; kk < 16; kk++) {
            float a[8], b[8];
#pragma unroll
            for (int i = 0; i < 8; i++) a[i] = As[kk][ty * 8 + i];
#pragma unroll
            for (int j = 0; j < 8; j++) b[j] = Bs[kk][tx * 8 + j];
#pragma unroll
            for (int i = 0; i < 8; i++)
#pragma unroll
                for (int j = 0; j < 8; j++)
                    acc[i][j] += a[i] * b[j];
        }
        __syncthreads();
    }

    // Epilogue: bias (+ tanh), vectorized stores.
#pragma unroll
    for (int i = 0; i < 8; i++) {
        int m = m0 + ty * 8 + i;
#pragma unroll
        for (int j = 0; j < 8; j += 4) {
            int n = n0 + tx * 8 + j;
            float4 v;
            v.x = acc[i][j + 0] + bias[n + 0];
            v.y = acc[i][j + 1] + bias[n + 1];
            v.z = acc[i][j + 2] + bias[n + 2];
            v.w = acc[i][j + 3] + bias[n + 3];
            if (TANH) {
                v.x = tanhf(v.x); v.y = tanhf(v.y);
                v.z = tanhf(v.z); v.w = tanhf(v.w);
            }
            *(float4*)(C + (size_t)m * N + n) = v;
        }
    }
}

// ---------------------------------------------------------------------------
// out = base + sum_{i<NK} c[i] * p[i]     (elementwise over BROWS*DIM, float4)
// ---------------------------------------------------------------------------
template<int NK>
__global__ void combine_kernel(const float* __restrict__ base, float* __restrict__ out,
                               const float* __restrict__ p0, const float* __restrict__ p1,
                               const float* __restrict__ p2, const float* __restrict__ p3,
                               const float* __restrict__ p4,
                               float c0, float c1, float c2, float c3, float c4)
{
    int i = blockIdx.x * blockDim.x + threadIdx.x;  // float4 index
    const int n4 = BROWS * DIM / 4;
    if (i >= n4) return;
    float4 v = ((const float4*)base)[i];
    if (NK >= 1) { float4 q = ((const float4*)p0)[i]; v.x += c0*q.x; v.y += c0*q.y; v.z += c0*q.z; v.w += c0*q.w; }
    if (NK >= 2) { float4 q = ((const float4*)p1)[i]; v.x += c1*q.x; v.y += c1*q.y; v.z += c1*q.z; v.w += c1*q.w; }
    if (NK >= 3) { float4 q = ((const float4*)p2)[i]; v.x += c2*q.x; v.y += c2*q.y; v.z += c2*q.z; v.w += c2*q.w; }
    if (NK >= 4) { float4 q = ((const float4*)p3)[i]; v.x += c3*q.x; v.y += c3*q.y; v.z += c3*q.z; v.w += c3*q.w; }
    if (NK >= 5) { float4 q = ((const float4*)p4)[i]; v.x += c4*q.x; v.y += c4*q.y; v.z += c4*q.z; v.w += c4*q.w; }
    ((float4*)out)[i] = v;
}

// Copy x -> g_y
__global__ void copy_kernel(const float* __restrict__ src, float* __restrict__ dst)
{
    int i = blockIdx.x * blockDim.x + threadIdx.x;
    const int n4 = BROWS * DIM / 4;
    if (i < n4) ((float4*)dst)[i] = ((const float4*)src)[i];
}

// Final projection: out[m] = dot(y[m,:], Wfc) + bfc   (one warp per row)
__global__ void proj_kernel(const float* __restrict__ y, const float* __restrict__ Wfc,
                            const float* __restrict__ bfc, float* __restrict__ out)
{
    int gwarp = (blockIdx.x * blockDim.x + threadIdx.x) >> 5;
    int lane  = threadIdx.x & 31;
    if (gwarp >= BROWS) return;
    const float* row = y + (size_t)gwarp * DIM;
    float s = 0.f;
#pragma unroll
    for (int d = lane; d < DIM; d += 32) s += row[d] * Wfc[d];
#pragma unroll
    for (int o = 16; o > 0; o >>= 1) s += __shfl_xor_sync(0xFFFFFFFFu, s, o);
    if (lane == 0) out[gwarp] = s + bfc[0];
}

// ---------------------------------------------------------------------------
// Host orchestration
// ---------------------------------------------------------------------------
static float* sym_addr(const void* sym)
{
    void* p = nullptr;
    cudaGetSymbolAddress(&p, sym);
    return (float*)p;
}

extern "C" void kernel_launch(void* const* d_in, const int* in_sizes, int n_in,
                              void* d_out, int out_size)
{
    const float* x   = (const float*)d_in[0];
    const float* W1  = (const float*)d_in[1];
    const float* b1  = (const float*)d_in[2];
    const float* W2  = (const float*)d_in[3];
    const float* b2  = (const float*)d_in[4];
    const float* Wfc = (const float*)d_in[5];
    const float* bfc = (const float*)d_in[6];
    float* out = (float*)d_out;

    float* y   = sym_addr(g_y);
    float* tmp = sym_addr(g_tmp);
    float* h   = sym_addr(g_h);
    float* kb  = sym_addr(g_k);
    float* k[6];
    for (int i = 0; i < 6; i++) k[i] = kb + (size_t)i * BROWS * DIM;

    const double dt = 1.0 / NSTEPS;
    // dopri5 tableau, pre-multiplied by dt
    const float A21 = (float)(dt * (1.0/5.0));
    const float A31 = (float)(dt * (3.0/40.0)),   A32 = (float)(dt * (9.0/40.0));
    const float A41 = (float)(dt * (44.0/45.0)),  A42 = (float)(dt * (-56.0/15.0)),  A43 = (float)(dt * (32.0/9.0));
    const float A51 = (float)(dt * (19372.0/6561.0)), A52 = (float)(dt * (-25360.0/2187.0)),
                A53 = (float)(dt * (64448.0/6561.0)), A54 = (float)(dt * (-212.0/729.0));
    const float A61 = (float)(dt * (9017.0/3168.0)), A62 = (float)(dt * (-355.0/33.0)),
                A63 = (float)(dt * (46732.0/5247.0)), A64 = (float)(dt * (49.0/176.0)),
                A65 = (float)(dt * (-5103.0/18656.0));
    const float B1 = (float)(dt * (35.0/384.0)),   B3 = (float)(dt * (500.0/1113.0)),
                B4 = (float)(dt * (125.0/192.0)),  B5 = (float)(dt * (-2187.0/6784.0)),
                B6 = (float)(dt * (11.0/84.0));

    const int n4 = BROWS * DIM / 4;
    const int cb = (n4 + 255) / 256;

    dim3 g1(HID / 128, BROWS / 128);   // GEMM1: N=512
    dim3 g2(DIM / 128, BROWS / 128);   // GEMM2: N=256

    auto feval = [&](const float* yin, float* kout) {
        sgemm_bias<true ><<<g1, 256>>>(yin, W1, b1, h,    BROWS, HID, DIM);
        sgemm_bias<false><<<g2, 256>>>(h,   W2, b2, kout, BROWS, DIM, HID);
    };

    copy_kernel<<<cb, 256>>>(x, y);

    for (int s = 0; s < NSTEPS; s++) {
        // stage 1
        feval(y, k[0]);
        // stage 2
        combine_kernel<1><<<cb, 256>>>(y, tmp, k[0], k[0], k[0], k[0], k[0],
                                       A21, 0, 0, 0, 0);
        feval(tmp, k[1]);
        // stage 3
        combine_kernel<2><<<cb, 256>>>(y, tmp, k[0], k[1], k[0], k[0], k[0],
                                       A31, A32, 0, 0, 0);
        feval(tmp, k[2]);
        // stage 4
        combine_kernel<3><<<cb, 256>>>(y, tmp, k[0], k[1], k[2], k[0], k[0],
                                       A41, A42, A43, 0, 0);
        feval(tmp, k[3]);
        // stage 5
        combine_kernel<4><<<cb, 256>>>(y, tmp, k[0], k[1], k[2], k[3], k[0],
                                       A51, A52, A53, A54, 0);
        feval(tmp, k[4]);
        // stage 6
        combine_kernel<5><<<cb, 256>>>(y, tmp, k[0], k[1], k[2], k[3], k[4],
                                       A61, A62, A63, A64, A65);
        feval(tmp, k[5]);
        // y update (b2 weight is 0; uses k1,k3,k4,k5,k6)
        combine_kernel<5><<<cb, 256>>>(y, y, k[0], k[2], k[3], k[4], k[5],
                                       B1, B3, B4, B5, B6);
    }

    proj_kernel<<<(BROWS * 32 + 255) / 256, 256>>>(y, Wfc, bfc, out);
}

// round 4
// speedup vs baseline: 2.5594x; 2.5594x over previous
#include <cuda_runtime.h>
#include <cstdint>
#include <cstddef>

// ---------------------------------------------------------------------------
// NeuralODE dopri5, 16 fixed steps.  f(y) = tanh(y @ W1 + b1) @ W2 + b2
// B=16384, D=256, H=512.  GEMMs via tf32 mma.sync (m16n8k8), fp32 accumulate.
// ---------------------------------------------------------------------------

#define BROWS 16384
#define DIM   256
#define HID   512
#define NSTEPS 16

__device__ float g_y  [BROWS * DIM];
__device__ float g_tmp[BROWS * DIM];
__device__ float g_h  [BROWS * HID];
__device__ float g_k  [6][BROWS * DIM];

// ---------------------------------------------------------------------------
// tf32 tensor-core GEMM: C[M,N] = A[M,K] * B[K,N] (+bias, optional tanh)
// Block tile 128x128, K-chunk 32. 256 threads = 8 warps in 2(m) x 4(n) grid,
// warp tile 64x32 -> 4 m-atoms x 4 n-atoms of m16n8k8.
// ---------------------------------------------------------------------------
__device__ __forceinline__ uint32_t f2tf32(float v) {
    uint32_t u;
    asm("cvt.rna.tf32.f32 %0, %1;" : "=r"(u) : "f"(v));
    return u;
}

template<bool TANH>
__global__ __launch_bounds__(256, 2)
void gemm_tf32(const float* __restrict__ A, const float* __restrict__ B,
               const float* __restrict__ bias, float* __restrict__ C,
               int M, int N, int K)
{
    __shared__ float As[128][36];   // [row][k], pad 36: frag loads conflict-free
    __shared__ float Bs[32][136];   // [k][col], pad 136: frag loads conflict-free

    const int tid = threadIdx.x;
    const int lane = tid & 31;
    const int wid  = tid >> 5;
    const int warp_m = wid & 1;         // 0..1  -> 64-row slice
    const int warp_n = wid >> 1;        // 0..3  -> 32-col slice
    const int grp  = lane >> 2;         // 0..7
    const int ctg  = lane & 3;          // 0..3

    const int m0 = blockIdx.y * 128;
    const int n0 = blockIdx.x * 128;

    float acc[4][4][4];
#pragma unroll
    for (int i = 0; i < 4; i++)
#pragma unroll
        for (int j = 0; j < 4; j++)
#pragma unroll
            for (int r = 0; r < 4; r++) acc[i][j][r] = 0.f;

    for (int k0 = 0; k0 < K; k0 += 32) {
        // Load A tile 128x32 (1024 float4 / 256 thr = 4 each), cvt to tf32 bits.
#pragma unroll
        for (int l = 0; l < 4; l++) {
            int f   = tid + l * 256;
            int row = f >> 3;
            int c4  = (f & 7) * 4;
            float4 v = *(const float4*)(A + (size_t)(m0 + row) * K + k0 + c4);
            As[row][c4 + 0] = __uint_as_float(f2tf32(v.x));
            As[row][c4 + 1] = __uint_as_float(f2tf32(v.y));
            As[row][c4 + 2] = __uint_as_float(f2tf32(v.z));
            As[row][c4 + 3] = __uint_as_float(f2tf32(v.w));
        }
        // Load B tile 32x128.
#pragma unroll
        for (int l = 0; l < 4; l++) {
            int f   = tid + l * 256;
            int row = f >> 5;
            int c4  = (f & 31) * 4;
            float4 v = *(const float4*)(B + (size_t)(k0 + row) * N + n0 + c4);
            Bs[row][c4 + 0] = __uint_as_float(f2tf32(v.x));
            Bs[row][c4 + 1] = __uint_as_float(f2tf32(v.y));
            Bs[row][c4 + 2] = __uint_as_float(f2tf32(v.z));
            Bs[row][c4 + 3] = __uint_as_float(f2tf32(v.w));
        }
        __syncthreads();

#pragma unroll
        for (int ks = 0; ks < 4; ks++) {
            const int kb = ks * 8;
            uint32_t af[4][4], bf[4][2];
#pragma unroll
            for (int im = 0; im < 4; im++) {
                int rb = warp_m * 64 + im * 16;
                af[im][0] = __float_as_uint(As[rb + grp    ][kb + ctg    ]);
                af[im][1] = __float_as_uint(As[rb + grp + 8][kb + ctg    ]);
                af[im][2] = __float_as_uint(As[rb + grp    ][kb + ctg + 4]);
                af[im][3] = __float_as_uint(As[rb + grp + 8][kb + ctg + 4]);
            }
#pragma unroll
            for (int in_ = 0; in_ < 4; in_++) {
                int cb = warp_n * 32 + in_ * 8;
                bf[in_][0] = __float_as_uint(Bs[kb + ctg    ][cb + grp]);
                bf[in_][1] = __float_as_uint(Bs[kb + ctg + 4][cb + grp]);
            }
#pragma unroll
            for (int im = 0; im < 4; im++)
#pragma unroll
                for (int in_ = 0; in_ < 4; in_++) {
                    asm volatile(
                        "mma.sync.aligned.m16n8k8.row.col.f32.tf32.tf32.f32 "
                        "{%0,%1,%2,%3}, {%4,%5,%6,%7}, {%8,%9}, {%0,%1,%2,%3};"
                        : "+f"(acc[im][in_][0]), "+f"(acc[im][in_][1]),
                          "+f"(acc[im][in_][2]), "+f"(acc[im][in_][3])
                        : "r"(af[im][0]), "r"(af[im][1]),
                          "r"(af[im][2]), "r"(af[im][3]),
                          "r"(bf[in_][0]), "r"(bf[in_][1]));
                }
        }
        __syncthreads();
    }

    // Epilogue: bias (+tanh), float2 stores.
#pragma unroll
    for (int im = 0; im < 4; im++) {
        int row0 = m0 + warp_m * 64 + im * 16 + grp;
        int row1 = row0 + 8;
#pragma unroll
        for (int in_ = 0; in_ < 4; in_++) {
            int col = n0 + warp_n * 32 + in_ * 8 + 2 * ctg;
            float bx = bias[col], by = bias[col + 1];
            float2 v0, v1;
            v0.x = acc[im][in_][0] + bx;  v0.y = acc[im][in_][1] + by;
            v1.x = acc[im][in_][2] + bx;  v1.y = acc[im][in_][3] + by;
            if (TANH) {
                v0.x = tanhf(v0.x); v0.y = tanhf(v0.y);
                v1.x = tanhf(v1.x); v1.y = tanhf(v1.y);
            }
            *(float2*)(C + (size_t)row0 * N + col) = v0;
            *(float2*)(C + (size_t)row1 * N + col) = v1;
        }
    }
}

// ---------------------------------------------------------------------------
// out = base + sum_{i<NK} c[i] * p[i]
// ---------------------------------------------------------------------------
template<int NK>
__global__ void combine_kernel(const float* __restrict__ base, float* __restrict__ out,
                               const float* __restrict__ p0, const float* __restrict__ p1,
                               const float* __restrict__ p2, const float* __restrict__ p3,
                               const float* __restrict__ p4,
                               float c0, float c1, float c2, float c3, float c4)
{
    int i = blockIdx.x * blockDim.x + threadIdx.x;
    const int n4 = BROWS * DIM / 4;
    if (i >= n4) return;
    float4 v = ((const float4*)base)[i];
    if (NK >= 1) { float4 q = ((const float4*)p0)[i]; v.x += c0*q.x; v.y += c0*q.y; v.z += c0*q.z; v.w += c0*q.w; }
    if (NK >= 2) { float4 q = ((const float4*)p1)[i]; v.x += c1*q.x; v.y += c1*q.y; v.z += c1*q.z; v.w += c1*q.w; }
    if (NK >= 3) { float4 q = ((const float4*)p2)[i]; v.x += c2*q.x; v.y += c2*q.y; v.z += c2*q.z; v.w += c2*q.w; }
    if (NK >= 4) { float4 q = ((const float4*)p3)[i]; v.x += c3*q.x; v.y += c3*q.y; v.z += c3*q.z; v.w += c3*q.w; }
    if (NK >= 5) { float4 q = ((const float4*)p4)[i]; v.x += c4*q.x; v.y += c4*q.y; v.z += c4*q.z; v.w += c4*q.w; }
    ((float4*)out)[i] = v;
}

__global__ void copy_kernel(const float* __restrict__ src, float* __restrict__ dst)
{
    int i = blockIdx.x * blockDim.x + threadIdx.x;
    const int n4 = BROWS * DIM / 4;
    if (i < n4) ((float4*)dst)[i] = ((const float4*)src)[i];
}

__global__ void proj_kernel(const float* __restrict__ y, const float* __restrict__ Wfc,
                            const float* __restrict__ bfc, float* __restrict__ out)
{
    int gwarp = (blockIdx.x * blockDim.x + threadIdx.x) >> 5;
    int lane  = threadIdx.x & 31;
    if (gwarp >= BROWS) return;
    const float* row = y + (size_t)gwarp * DIM;
    float s = 0.f;
#pragma unroll
    for (int d = lane; d < DIM; d += 32) s += row[d] * Wfc[d];
#pragma unroll
    for (int o = 16; o > 0; o >>= 1) s += __shfl_xor_sync(0xFFFFFFFFu, s, o);
    if (lane == 0) out[gwarp] = s + bfc[0];
}

// ---------------------------------------------------------------------------
static float* sym_addr(const void* sym)
{
    void* p = nullptr;
    cudaGetSymbolAddress(&p, sym);
    return (float*)p;
}

extern "C" void kernel_launch(void* const* d_in, const int* in_sizes, int n_in,
                              void* d_out, int out_size)
{
    const float* x   = (const float*)d_in[0];
    const float* W1  = (const float*)d_in[1];
    const float* b1  = (const float*)d_in[2];
    const float* W2  = (const float*)d_in[3];
    const float* b2  = (const float*)d_in[4];
    const float* Wfc = (const float*)d_in[5];
    const float* bfc = (const float*)d_in[6];
    float* out = (float*)d_out;

    float* y   = sym_addr(g_y);
    float* tmp = sym_addr(g_tmp);
    float* h   = sym_addr(g_h);
    float* kb  = sym_addr(g_k);
    float* k[6];
    for (int i = 0; i < 6; i++) k[i] = kb + (size_t)i * BROWS * DIM;

    const double dt = 1.0 / NSTEPS;
    const float A21 = (float)(dt * (1.0/5.0));
    const float A31 = (float)(dt * (3.0/40.0)),   A32 = (float)(dt * (9.0/40.0));
    const float A41 = (float)(dt * (44.0/45.0)),  A42 = (float)(dt * (-56.0/15.0)),  A43 = (float)(dt * (32.0/9.0));
    const float A51 = (float)(dt * (19372.0/6561.0)), A52 = (float)(dt * (-25360.0/2187.0)),
                A53 = (float)(dt * (64448.0/6561.0)), A54 = (float)(dt * (-212.0/729.0));
    const float A61 = (float)(dt * (9017.0/3168.0)), A62 = (float)(dt * (-355.0/33.0)),
                A63 = (float)(dt * (46732.0/5247.0)), A64 = (float)(dt * (49.0/176.0)),
                A65 = (float)(dt * (-5103.0/18656.0));
    const float B1 = (float)(dt * (35.0/384.0)),   B3 = (float)(dt * (500.0/1113.0)),
                B4 = (float)(dt * (125.0/192.0)),  B5 = (float)(dt * (-2187.0/6784.0)),
                B6 = (float)(dt * (11.0/84.0));

    const int n4 = BROWS * DIM / 4;
    const int cb = (n4 + 255) / 256;

    dim3 g1(HID / 128, BROWS / 128);   // GEMM1
    dim3 g2(DIM / 128, BROWS / 128);   // GEMM2

    auto feval = [&](const float* yin, float* kout) {
        gemm_tf32<true ><<<g1, 256>>>(yin, W1, b1, h,    BROWS, HID, DIM);
        gemm_tf32<false><<<g2, 256>>>(h,   W2, b2, kout, BROWS, DIM, HID);
    };

    copy_kernel<<<cb, 256>>>(x, y);

    for (int s = 0; s < NSTEPS; s++) {
        feval(y, k[0]);
        combine_kernel<1><<<cb, 256>>>(y, tmp, k[0], k[0], k[0], k[0], k[0],
                                       A21, 0, 0, 0, 0);
        feval(tmp, k[1]);
        combine_kernel<2><<<cb, 256>>>(y, tmp, k[0], k[1], k[0], k[0], k[0],
                                       A31, A32, 0, 0, 0);
        feval(tmp, k[2]);
        combine_kernel<3><<<cb, 256>>>(y, tmp, k[0], k[1], k[2], k[0], k[0],
                                       A41, A42, A43, 0, 0);
        feval(tmp, k[3]);
        combine_kernel<4><<<cb, 256>>>(y, tmp, k[0], k[1], k[2], k[3], k[0],
                                       A51, A52, A53, A54, 0);
        feval(tmp, k[4]);
        combine_kernel<5><<<cb, 256>>>(y, tmp, k[0], k[1], k[2], k[3], k[4],
                                       A61, A62, A63, A64, A65);
        feval(tmp, k[5]);
        combine_kernel<5><<<cb, 256>>>(y, y, k[0], k[2], k[3], k[4], k[5],
                                       B1, B3, B4, B5, B6);
    }

    proj_kernel<<<(BROWS * 32 + 255) / 256, 256>>>(y, Wfc, bfc, out);
}

// round 17
// speedup vs baseline: 3.4569x; 1.3507x over previous
#include <cuda_runtime.h>
#include <cuda_fp16.h>
#include <cstdint>
#include <cstddef>

// ===========================================================================
// NeuralODE dopri5, 16 steps.  f(y) = tanh(y @ W1 + b1) @ W2 + b2
// B=16384, D=256, H=512.
// EXACT Round-4 orchestration (separate combine kernels, tmp buffer, tanhf).
// GEMM datapath switched tf32 m16n8k8 -> fp16 m16n8k16 (fp32 accumulate):
// half the tensor instructions per FLOP. Weights pre-transposed to half [N][K].
// ===========================================================================

#define BROWS 16384
#define DIM   256
#define HID   512
#define NSTEPS 16

__device__ float g_y  [BROWS * DIM];           // state
__device__ float g_tmp[BROWS * DIM];           // stage input ytmp
__device__ float g_h  [BROWS * HID];           // hidden activations
__device__ float g_k  [6][BROWS * DIM];        // k1..k6
__device__ __half g_w1t[HID * DIM];            // W1^T as half, [n=HID][k=DIM]
__device__ __half g_w2t[DIM * HID];            // W2^T as half, [n=DIM][k=HID]

// ---------------------------------------------------------------------------
// fp16 tensor-core GEMM: C[M,N] = A[M,K](fp32,cvt) * Bt[N,K](half) (+bias,tanh)
// Block tile 128x128, K-chunk 32. 256 threads = 8 warps (2m x 4n), warp 64x32.
// mma.m16n8k16.row.col.f32.f16.f16.f32; 2 k-steps of 16 per chunk.
// ---------------------------------------------------------------------------
template<bool TANH>
__global__ __launch_bounds__(256, 2)
void gemm_fp16(const float* __restrict__ A, const __half* __restrict__ Bt,
               const float* __restrict__ bias, float* __restrict__ C,
               int M, int N, int K)
{
    __shared__ __align__(16) __half As[128][40];   // [row][k], pad to 40
    __shared__ __align__(16) __half Bs[128][40];   // [n][k],  pad to 40

    const int tid = threadIdx.x;
    const int lane = tid & 31;
    const int wid  = tid >> 5;
    const int warp_m = wid & 1;         // 0..1  -> 64-row slice
    const int warp_n = wid >> 1;        // 0..3  -> 32-col slice
    const int grp  = lane >> 2;         // 0..7
    const int ctg  = lane & 3;          // 0..3

    const int m0 = blockIdx.y * 128;
    const int n0 = blockIdx.x * 128;

    float acc[4][4][4];
#pragma unroll
    for (int i = 0; i < 4; i++)
#pragma unroll
        for (int j = 0; j < 4; j++)
#pragma unroll
            for (int r = 0; r < 4; r++) acc[i][j][r] = 0.f;

    for (int k0 = 0; k0 < K; k0 += 32) {
        // A tile 128x32: fp32 gmem -> cvt half2 -> smem. 1024 float4 loads.
#pragma unroll
        for (int l = 0; l < 4; l++) {
            int f   = tid + l * 256;
            int row = f >> 3;
            int c4  = (f & 7) * 4;
            float4 v = *(const float4*)(A + (size_t)(m0 + row) * K + k0 + c4);
            __half2 h01 = __floats2half2_rn(v.x, v.y);
            __half2 h23 = __floats2half2_rn(v.z, v.w);
            uint2 pk;
            pk.x = *reinterpret_cast<uint32_t*>(&h01);
            pk.y = *reinterpret_cast<uint32_t*>(&h23);
            *reinterpret_cast<uint2*>(&As[row][c4]) = pk;
        }
        // B tile 128(n) x 32(k) halves from transposed weights: raw uint4 copy.
#pragma unroll
        for (int l = 0; l < 2; l++) {
            int f   = tid + l * 256;
            int row = f >> 2;
            int seg = (f & 3) * 8;
            uint4 v = *reinterpret_cast<const uint4*>(
                Bt + (size_t)(n0 + row) * K + k0 + seg);
            *reinterpret_cast<uint4*>(&Bs[row][seg]) = v;
        }
        __syncthreads();

        // 2 k-steps of 16
#pragma unroll
        for (int ks = 0; ks < 2; ks++) {
            const int kb = ks * 16;
            uint32_t af[4][4], bf[4][2];
#pragma unroll
            for (int im = 0; im < 4; im++) {
                int rb = warp_m * 64 + im * 16;
                af[im][0] = *reinterpret_cast<const uint32_t*>(&As[rb + grp    ][kb + 2*ctg    ]);
                af[im][1] = *reinterpret_cast<const uint32_t*>(&As[rb + grp + 8][kb + 2*ctg    ]);
                af[im][2] = *reinterpret_cast<const uint32_t*>(&As[rb + grp    ][kb + 2*ctg + 8]);
                af[im][3] = *reinterpret_cast<const uint32_t*>(&As[rb + grp + 8][kb + 2*ctg + 8]);
            }
#pragma unroll
            for (int in_ = 0; in_ < 4; in_++) {
                int cb = warp_n * 32 + in_ * 8;
                bf[in_][0] = *reinterpret_cast<const uint32_t*>(&Bs[cb + grp][kb + 2*ctg    ]);
                bf[in_][1] = *reinterpret_cast<const uint32_t*>(&Bs[cb + grp][kb + 2*ctg + 8]);
            }
#pragma unroll
            for (int im = 0; im < 4; im++)
#pragma unroll
                for (int in_ = 0; in_ < 4; in_++) {
                    asm volatile(
                        "mma.sync.aligned.m16n8k16.row.col.f32.f16.f16.f32 "
                        "{%0,%1,%2,%3}, {%4,%5,%6,%7}, {%8,%9}, {%0,%1,%2,%3};"
                        : "+f"(acc[im][in_][0]), "+f"(acc[im][in_][1]),
                          "+f"(acc[im][in_][2]), "+f"(acc[im][in_][3])
                        : "r"(af[im][0]), "r"(af[im][1]),
                          "r"(af[im][2]), "r"(af[im][3]),
                          "r"(bf[in_][0]), "r"(bf[in_][1]));
                }
        }
        __syncthreads();
    }

    // Epilogue: bias (+ tanh), float2 stores.  (identical to Round 4)
#pragma unroll
    for (int im = 0; im < 4; im++) {
        int row0 = m0 + warp_m * 64 + im * 16 + grp;
        int row1 = row0 + 8;
#pragma unroll
        for (int in_ = 0; in_ < 4; in_++) {
            int col = n0 + warp_n * 32 + in_ * 8 + 2 * ctg;
            float bx = bias[col], by = bias[col + 1];
            float2 v0, v1;
            v0.x = acc[im][in_][0] + bx;  v0.y = acc[im][in_][1] + by;
            v1.x = acc[im][in_][2] + bx;  v1.y = acc[im][in_][3] + by;
            if (TANH) {
                v0.x = tanhf(v0.x); v0.y = tanhf(v0.y);
                v1.x = tanhf(v1.x); v1.y = tanhf(v1.y);
            }
            *(float2*)(C + (size_t)row0 * N + col) = v0;
            *(float2*)(C + (size_t)row1 * N + col) = v1;
        }
    }
}

// ---------------------------------------------------------------------------
// Weight transpose to half (once per launch; tiny, ~400K elements total)
// ---------------------------------------------------------------------------
__global__ void conv_w1t(const float* __restrict__ W1)   // W1: [k=DIM][n=HID]
{
    int i = blockIdx.x * blockDim.x + threadIdx.x;
    if (i >= HID * DIM) return;
    int n = i / DIM, k = i % DIM;
    g_w1t[i] = __float2half_rn(W1[(size_t)k * HID + n]);
}
__global__ void conv_w2t(const float* __restrict__ W2)   // W2: [k=HID][n=DIM]
{
    int i = blockIdx.x * blockDim.x + threadIdx.x;
    if (i >= DIM * HID) return;
    int n = i / HID, k = i % HID;
    g_w2t[i] = __float2half_rn(W2[(size_t)k * DIM + n]);
}

// ---------------------------------------------------------------------------
// out = base + sum_{i<NK} c[i] * p[i]      (verbatim Round 4)
// ---------------------------------------------------------------------------
template<int NK>
__global__ void combine_kernel(const float* __restrict__ base, float* __restrict__ out,
                               const float* __restrict__ p0, const float* __restrict__ p1,
                               const float* __restrict__ p2, const float* __restrict__ p3,
                               const float* __restrict__ p4,
                               float c0, float c1, float c2, float c3, float c4)
{
    int i = blockIdx.x * blockDim.x + threadIdx.x;
    const int n4 = BROWS * DIM / 4;
    if (i >= n4) return;
    float4 v = ((const float4*)base)[i];
    if (NK >= 1) { float4 q = ((const float4*)p0)[i]; v.x += c0*q.x; v.y += c0*q.y; v.z += c0*q.z; v.w += c0*q.w; }
    if (NK >= 2) { float4 q = ((const float4*)p1)[i]; v.x += c1*q.x; v.y += c1*q.y; v.z += c1*q.z; v.w += c1*q.w; }
    if (NK >= 3) { float4 q = ((const float4*)p2)[i]; v.x += c2*q.x; v.y += c2*q.y; v.z += c2*q.z; v.w += c2*q.w; }
    if (NK >= 4) { float4 q = ((const float4*)p3)[i]; v.x += c3*q.x; v.y += c3*q.y; v.z += c3*q.z; v.w += c3*q.w; }
    if (NK >= 5) { float4 q = ((const float4*)p4)[i]; v.x += c4*q.x; v.y += c4*q.y; v.z += c4*q.z; v.w += c4*q.w; }
    ((float4*)out)[i] = v;
}

__global__ void copy_kernel(const float* __restrict__ src, float* __restrict__ dst)
{
    int i = blockIdx.x * blockDim.x + threadIdx.x;
    const int n4 = BROWS * DIM / 4;
    if (i < n4) ((float4*)dst)[i] = ((const float4*)src)[i];
}

__global__ void proj_kernel(const float* __restrict__ y, const float* __restrict__ Wfc,
                            const float* __restrict__ bfc, float* __restrict__ out)
{
    int gwarp = (blockIdx.x * blockDim.x + threadIdx.x) >> 5;
    int lane  = threadIdx.x & 31;
    if (gwarp >= BROWS) return;
    const float* row = y + (size_t)gwarp * DIM;
    float s = 0.f;
#pragma unroll
    for (int d = lane; d < DIM; d += 32) s += row[d] * Wfc[d];
#pragma unroll
    for (int o = 16; o > 0; o >>= 1) s += __shfl_xor_sync(0xFFFFFFFFu, s, o);
    if (lane == 0) out[gwarp] = s + bfc[0];
}

// ---------------------------------------------------------------------------
static float* sym_addr(const void* sym)
{
    void* p = nullptr;
    cudaGetSymbolAddress(&p, sym);
    return (float*)p;
}

extern "C" void kernel_launch(void* const* d_in, const int* in_sizes, int n_in,
                              void* d_out, int out_size)
{
    const float* x   = (const float*)d_in[0];
    const float* W1  = (const float*)d_in[1];
    const float* b1  = (const float*)d_in[2];
    const float* W2  = (const float*)d_in[3];
    const float* b2  = (const float*)d_in[4];
    const float* Wfc = (const float*)d_in[5];
    const float* bfc = (const float*)d_in[6];
    float* out = (float*)d_out;

    float* y   = sym_addr(g_y);
    float* tmp = sym_addr(g_tmp);
    float* h   = sym_addr(g_h);
    float* kb  = sym_addr(g_k);
    __half* w1t = (__half*)sym_addr(g_w1t);
    __half* w2t = (__half*)sym_addr(g_w2t);
    float* k[6];
    for (int i = 0; i < 6; i++) k[i] = kb + (size_t)i * BROWS * DIM;

    const double dt = 1.0 / NSTEPS;
    const float A21 = (float)(dt * (1.0/5.0));
    const float A31 = (float)(dt * (3.0/40.0)),   A32 = (float)(dt * (9.0/40.0));
    const float A41 = (float)(dt * (44.0/45.0)),  A42 = (float)(dt * (-56.0/15.0)),  A43 = (float)(dt * (32.0/9.0));
    const float A51 = (float)(dt * (19372.0/6561.0)), A52 = (float)(dt * (-25360.0/2187.0)),
                A53 = (float)(dt * (64448.0/6561.0)), A54 = (float)(dt * (-212.0/729.0));
    const float A61 = (float)(dt * (9017.0/3168.0)), A62 = (float)(dt * (-355.0/33.0)),
                A63 = (float)(dt * (46732.0/5247.0)), A64 = (float)(dt * (49.0/176.0)),
                A65 = (float)(dt * (-5103.0/18656.0));
    const float B1 = (float)(dt * (35.0/384.0)),   B3 = (float)(dt * (500.0/1113.0)),
                B4 = (float)(dt * (125.0/192.0)),  B5 = (float)(dt * (-2187.0/6784.0)),
                B6 = (float)(dt * (11.0/84.0));

    const int n4 = BROWS * DIM / 4;
    const int cb = (n4 + 255) / 256;

    conv_w1t<<<(HID * DIM + 255) / 256, 256>>>(W1);
    conv_w2t<<<(DIM * HID + 255) / 256, 256>>>(W2);
    copy_kernel<<<cb, 256>>>(x, y);

    const dim3 g1(HID / 128, BROWS / 128);   // (4, 128)
    const dim3 g2(DIM / 128, BROWS / 128);   // (2, 128)

    auto feval = [&](const float* yin, float* kout) {
        gemm_fp16<true ><<<g1, 256>>>(yin, w1t, b1, h,    BROWS, HID, DIM);
        gemm_fp16<false><<<g2, 256>>>(h,   w2t, b2, kout, BROWS, DIM, HID);
    };

    for (int s = 0; s < NSTEPS; s++) {
        // stage 1
        feval(y, k[0]);
        // stage 2
        combine_kernel<1><<<cb, 256>>>(y, tmp, k[0], k[0], k[0], k[0], k[0],
                                       A21, 0, 0, 0, 0);
        feval(tmp, k[1]);
        // stage 3
        combine_kernel<2><<<cb, 256>>>(y, tmp, k[0], k[1], k[0], k[0], k[0],
                                       A31, A32, 0, 0, 0);
        feval(tmp, k[2]);
        // stage 4
        combine_kernel<3><<<cb, 256>>>(y, tmp, k[0], k[1], k[2], k[0], k[0],
                                       A41, A42, A43, 0, 0);
        feval(tmp, k[3]);
        // stage 5
        combine_kernel<4><<<cb, 256>>>(y, tmp, k[0], k[1], k[2], k[3], k[0],
                                       A51, A52, A53, A54, 0);
        feval(tmp, k[4]);
        // stage 6
        combine_kernel<5><<<cb, 256>>>(y, tmp, k[0], k[1], k[2], k[3], k[4],
                                       A61, A62, A63, A64, A65);
        feval(tmp, k[5]);
        // y update (uses k1,k3,k4,k5,k6)
        combine_kernel<5><<<cb, 256>>>(y, y, k[0], k[2], k[3], k[4], k[5],
                                       B1, B3, B4, B5, B6);
    }

    proj_kernel<<<(BROWS * 32 + 255) / 256, 256>>>(y, Wfc, bfc, out);
}